// round 2
// baseline (speedup 1.0000x reference)
#include <cuda_runtime.h>
#include <cuda_bf16.h>
#include <cstdint>

// Problem constants
#define BB   2
#define SS   2048
#define HID  2048
#define NH   32
#define NKV  8
#define DH   64
#define ROWS (BB * SS)          // 4096

typedef __nv_bfloat16 bf16;

// ---------------------------------------------------------------------------
// Scratch (static device arrays; allocation APIs are forbidden)
// ---------------------------------------------------------------------------
__device__ float g_qg [(size_t)ROWS * 4096];   // q (cols 0..2047, RoPE'd in place) | gate
__device__ float g_k  [(size_t)ROWS * 512];    // k, RoPE'd in place
__device__ bf16  g_hid_h[(size_t)ROWS * HID],  g_hid_l[(size_t)ROWS * HID];
__device__ bf16  g_wqt_h[(size_t)4096 * HID],  g_wqt_l[(size_t)4096 * HID];   // wq^T [4096][2048]
__device__ bf16  g_wkt_h[(size_t)512  * HID],  g_wkt_l[(size_t)512  * HID];   // wk^T [512][2048]
__device__ bf16  g_wot_h[(size_t)HID  * HID],  g_wot_l[(size_t)HID  * HID];   // wo^T [2048][2048]
__device__ bf16  g_ctx_h[(size_t)ROWS * HID],  g_ctx_l[(size_t)ROWS * HID];

// ---------------------------------------------------------------------------
// Elementwise fp32 -> (bf16 hi, bf16 lo) split, float4 vectorized.
// ---------------------------------------------------------------------------
__global__ void split_kernel(const float* __restrict__ src,
                             bf16* __restrict__ h, bf16* __restrict__ l, int n4)
{
    int i = blockIdx.x * blockDim.x + threadIdx.x;
    if (i >= n4) return;
    float4 v = ((const float4*)src)[i];
    bf16 h0 = __float2bfloat16(v.x), h1 = __float2bfloat16(v.y);
    bf16 h2 = __float2bfloat16(v.z), h3 = __float2bfloat16(v.w);
    bf16 l0 = __float2bfloat16(v.x - __bfloat162float(h0));
    bf16 l1 = __float2bfloat16(v.y - __bfloat162float(h1));
    bf16 l2 = __float2bfloat16(v.z - __bfloat162float(h2));
    bf16 l3 = __float2bfloat16(v.w - __bfloat162float(h3));
    h[i * 4 + 0] = h0; h[i * 4 + 1] = h1; h[i * 4 + 2] = h2; h[i * 4 + 3] = h3;
    l[i * 4 + 0] = l0; l[i * 4 + 1] = l1; l[i * 4 + 2] = l2; l[i * 4 + 3] = l3;
}

// ---------------------------------------------------------------------------
// Transpose + split: src [K][N] fp32 -> th/tl [N][K] bf16. 32x32 smem tile.
// Block (32,8), grid (N/32, K/32).
// ---------------------------------------------------------------------------
__global__ void transpose_split(const float* __restrict__ src,
                                bf16* __restrict__ th, bf16* __restrict__ tl,
                                int K, int N)
{
    __shared__ float tile[32][33];
    int kb = blockIdx.y * 32, nb = blockIdx.x * 32;
    int tx = threadIdx.x, ty = threadIdx.y;
    #pragma unroll
    for (int i = 0; i < 32; i += 8)
        tile[ty + i][tx] = src[(size_t)(kb + ty + i) * N + nb + tx];
    __syncthreads();
    #pragma unroll
    for (int i = 0; i < 32; i += 8) {
        float v = tile[tx][ty + i];
        bf16 hh = __float2bfloat16(v);
        bf16 ll = __float2bfloat16(v - __bfloat162float(hh));
        size_t o = (size_t)(nb + ty + i) * K + kb + tx;
        th[o] = hh;
        tl[o] = ll;
    }
}

// ---------------------------------------------------------------------------
// 3-pass bf16-split TN GEMM on tensor cores:
//   C[M][N](f32) = (Ah+Al)[M][K] @ (Bh+Bl)[N][K]^T, via Ah.Bh + Ah.Bl + Al.Bh
// mma.sync.m16n8k16.row.col.f32.bf16.bf16.f32
// CTA tile 128x128x32, 8 warps (2x4), warp tile 64x32, register prefetch.
// Requires M%128==0, N%128==0, K%32==0 (true for all calls here).
// ---------------------------------------------------------------------------
#define GSTRIDE 40   // smem row stride in bf16 units (padded: conflict-free frags)

__device__ __forceinline__ void mma16816(float* c, const uint32_t* a, const uint32_t* b)
{
    asm volatile(
        "mma.sync.aligned.m16n8k16.row.col.f32.bf16.bf16.f32 "
        "{%0,%1,%2,%3}, {%4,%5,%6,%7}, {%8,%9}, {%0,%1,%2,%3};"
        : "+f"(c[0]), "+f"(c[1]), "+f"(c[2]), "+f"(c[3])
        : "r"(a[0]), "r"(a[1]), "r"(a[2]), "r"(a[3]), "r"(b[0]), "r"(b[1]));
}

__global__ void __launch_bounds__(256, 1)
gemm_bf16split(const bf16* __restrict__ Ah, const bf16* __restrict__ Al,
               const bf16* __restrict__ Bh, const bf16* __restrict__ Bl,
               float* __restrict__ C, int M, int N, int K)
{
    __shared__ bf16 sAh[128 * GSTRIDE], sAl[128 * GSTRIDE];
    __shared__ bf16 sBh[128 * GSTRIDE], sBl[128 * GSTRIDE];

    const int tid  = threadIdx.x;
    const int warp = tid >> 5, lane = tid & 31;
    const int g    = lane >> 2, t = lane & 3;
    const int wm   = (warp & 1) * 64;       // warp row offset in CTA tile
    const int wn   = (warp >> 1) * 32;      // warp col offset
    const int brow = blockIdx.y * 128;
    const int bcol = blockIdx.x * 128;

    // gmem load mapping: per array, 2 uint4 per thread per stage
    // linear i = j*256 + tid; row = i>>2 (0..127); k0 = (i&3)*8
    const int r0 = tid >> 2,           k00 = (tid & 3) * 8;
    const int r1 = (tid + 256) >> 2,   k01 = ((tid + 256) & 3) * 8;

    const bf16* pAh = Ah + (size_t)brow * K;
    const bf16* pAl = Al + (size_t)brow * K;
    const bf16* pBh = Bh + (size_t)bcol * K;
    const bf16* pBl = Bl + (size_t)bcol * K;

    float acc[4][4][4] = {};   // [m_atom][n_atom][frag]

    uint4 ra_h[2], ra_l[2], rb_h[2], rb_l[2];

    // initial prefetch (kt = 0)
    ra_h[0] = *(const uint4*)(pAh + (size_t)r0 * K + k00);
    ra_h[1] = *(const uint4*)(pAh + (size_t)r1 * K + k01);
    ra_l[0] = *(const uint4*)(pAl + (size_t)r0 * K + k00);
    ra_l[1] = *(const uint4*)(pAl + (size_t)r1 * K + k01);
    rb_h[0] = *(const uint4*)(pBh + (size_t)r0 * K + k00);
    rb_h[1] = *(const uint4*)(pBh + (size_t)r1 * K + k01);
    rb_l[0] = *(const uint4*)(pBl + (size_t)r0 * K + k00);
    rb_l[1] = *(const uint4*)(pBl + (size_t)r1 * K + k01);

    for (int kt = 0; kt < K; kt += 32) {
        // regs -> smem
        *(uint4*)&sAh[r0 * GSTRIDE + k00] = ra_h[0];
        *(uint4*)&sAh[r1 * GSTRIDE + k01] = ra_h[1];
        *(uint4*)&sAl[r0 * GSTRIDE + k00] = ra_l[0];
        *(uint4*)&sAl[r1 * GSTRIDE + k01] = ra_l[1];
        *(uint4*)&sBh[r0 * GSTRIDE + k00] = rb_h[0];
        *(uint4*)&sBh[r1 * GSTRIDE + k01] = rb_h[1];
        *(uint4*)&sBl[r0 * GSTRIDE + k00] = rb_l[0];
        *(uint4*)&sBl[r1 * GSTRIDE + k01] = rb_l[1];
        __syncthreads();

        if (kt + 32 < K) {
            int kn = kt + 32;
            ra_h[0] = *(const uint4*)(pAh + (size_t)r0 * K + kn + k00);
            ra_h[1] = *(const uint4*)(pAh + (size_t)r1 * K + kn + k01);
            ra_l[0] = *(const uint4*)(pAl + (size_t)r0 * K + kn + k00);
            ra_l[1] = *(const uint4*)(pAl + (size_t)r1 * K + kn + k01);
            rb_h[0] = *(const uint4*)(pBh + (size_t)r0 * K + kn + k00);
            rb_h[1] = *(const uint4*)(pBh + (size_t)r1 * K + kn + k01);
            rb_l[0] = *(const uint4*)(pBl + (size_t)r0 * K + kn + k00);
            rb_l[1] = *(const uint4*)(pBl + (size_t)r1 * K + kn + k01);
        }

        #pragma unroll
        for (int s = 0; s < 2; s++) {            // two k16 steps per stage
            const int kp0 = s * 8 + t;           // u32 (bf16-pair) index
            uint32_t fah[4][4], fal[4][4], fbh[4][2], fbl[4][2];

            #pragma unroll
            for (int ma = 0; ma < 4; ma++) {
                int ra = wm + ma * 16 + g;
                fah[ma][0] = *(const uint32_t*)&sAh[(ra)     * GSTRIDE + (kp0)     * 2];
                fah[ma][1] = *(const uint32_t*)&sAh[(ra + 8) * GSTRIDE + (kp0)     * 2];
                fah[ma][2] = *(const uint32_t*)&sAh[(ra)     * GSTRIDE + (kp0 + 4) * 2];
                fah[ma][3] = *(const uint32_t*)&sAh[(ra + 8) * GSTRIDE + (kp0 + 4) * 2];
                fal[ma][0] = *(const uint32_t*)&sAl[(ra)     * GSTRIDE + (kp0)     * 2];
                fal[ma][1] = *(const uint32_t*)&sAl[(ra + 8) * GSTRIDE + (kp0)     * 2];
                fal[ma][2] = *(const uint32_t*)&sAl[(ra)     * GSTRIDE + (kp0 + 4) * 2];
                fal[ma][3] = *(const uint32_t*)&sAl[(ra + 8) * GSTRIDE + (kp0 + 4) * 2];
            }
            #pragma unroll
            for (int na = 0; na < 4; na++) {
                int rb = wn + na * 8 + g;
                fbh[na][0] = *(const uint32_t*)&sBh[rb * GSTRIDE + (kp0)     * 2];
                fbh[na][1] = *(const uint32_t*)&sBh[rb * GSTRIDE + (kp0 + 4) * 2];
                fbl[na][0] = *(const uint32_t*)&sBl[rb * GSTRIDE + (kp0)     * 2];
                fbl[na][1] = *(const uint32_t*)&sBl[rb * GSTRIDE + (kp0 + 4) * 2];
            }

            #pragma unroll
            for (int ma = 0; ma < 4; ma++)
                #pragma unroll
                for (int na = 0; na < 4; na++) {
                    mma16816(acc[ma][na], fah[ma], fbh[na]);   // Ah.Bh
                    mma16816(acc[ma][na], fah[ma], fbl[na]);   // Ah.Bl
                    mma16816(acc[ma][na], fal[ma], fbh[na]);   // Al.Bh
                }
        }
        __syncthreads();
    }

    // epilogue: fp32 C
    #pragma unroll
    for (int ma = 0; ma < 4; ma++) {
        int row = brow + wm + ma * 16 + g;
        #pragma unroll
        for (int na = 0; na < 4; na++) {
            int col = bcol + wn + na * 8 + t * 2;
            float2 v0 = {acc[ma][na][0], acc[ma][na][1]};
            float2 v1 = {acc[ma][na][2], acc[ma][na][3]};
            *(float2*)&C[(size_t)row       * N + col] = v0;
            *(float2*)&C[(size_t)(row + 8) * N + col] = v1;
        }
    }
}

// ---------------------------------------------------------------------------
// RoPE (in place). x viewed as [ROWS][stride]; heads at col h*64.
// ---------------------------------------------------------------------------
__global__ void rope_kernel(float* __restrict__ x,
                            const float* __restrict__ ct,
                            const float* __restrict__ st,
                            int stride, int nh)
{
    int idx = blockIdx.x * blockDim.x + threadIdx.x;
    int d = idx & 31;
    int h = (idx >> 5) % nh;
    int r = idx / (32 * nh);
    if (r >= ROWS) return;
    int s = r & (SS - 1);

    float* p = x + (size_t)r * stride + h * 64;
    float c0 = ct[s * 64 + d],      s0 = st[s * 64 + d];
    float c1 = ct[s * 64 + d + 32], s1 = st[s * 64 + d + 32];
    float x0 = p[d], x1 = p[d + 32];
    p[d]      = x0 * c0 - x1 * s0;
    p[d + 32] = x1 * c1 + x0 * s1;
}

// ---------------------------------------------------------------------------
// Flash-style causal attention (fp32), reference quirk: out = softmax(QK^T)@K.
// Epilogue: * sigmoid(gate), then write ctx as split bf16 hi/lo.
// ---------------------------------------------------------------------------
#define ATTN_SMEM ((64 * 64 + 64 * 65 + 64 * 64) * 4)   // 49408 B

__global__ void __launch_bounds__(256, 2)
attn_kernel(const float* __restrict__ qg, const float* __restrict__ kbuf,
            bf16* __restrict__ ctx_h, bf16* __restrict__ ctx_l)
{
    extern __shared__ float sm[];
    float* Qs = sm;                   // [64][64]
    float* Ks = sm + 64 * 64;         // [64][65] padded
    float* Ps = Ks + 64 * 65;         // [64][64]

    const int qt  = gridDim.x - 1 - blockIdx.x;   // longest blocks first
    const int h   = blockIdx.y;
    const int b   = blockIdx.z;
    const int kvh = h >> 2;                       // G = 4
    const int tid = threadIdx.x;
    const int tx  = tid & 15;
    const int ty  = tid >> 4;

    #pragma unroll
    for (int i = 0; i < 16; i++) {
        int lin = i * 256 + tid;
        int r = lin >> 6, c = lin & 63;
        Qs[r * 64 + c] = qg[((size_t)(b * SS + qt * 64 + r)) * 4096 + h * 64 + c];
    }

    float m_i[4] = {-1e30f, -1e30f, -1e30f, -1e30f};
    float l_i[4] = {0.f, 0.f, 0.f, 0.f};
    float Ot[4][4] = {};

    for (int kt = 0; kt <= qt; kt++) {
        __syncthreads();
        #pragma unroll
        for (int i = 0; i < 16; i++) {
            int lin = i * 256 + tid;
            int r = lin >> 6, c = lin & 63;
            Ks[r * 65 + c] = kbuf[((size_t)(b * SS + kt * 64 + r)) * 512 + kvh * 64 + c];
        }
        __syncthreads();

        float sacc[4][4] = {};
        #pragma unroll 4
        for (int d = 0; d < 64; d++) {
            float qv[4], kv[4];
            #pragma unroll
            for (int i = 0; i < 4; i++) qv[i] = Qs[(ty * 4 + i) * 64 + d];
            #pragma unroll
            for (int j = 0; j < 4; j++) kv[j] = Ks[(tx * 4 + j) * 65 + d];
            #pragma unroll
            for (int i = 0; i < 4; i++)
                #pragma unroll
                for (int j = 0; j < 4; j++)
                    sacc[i][j] = fmaf(qv[i], kv[j], sacc[i][j]);
        }

        if (kt == qt) {
            #pragma unroll
            for (int i = 0; i < 4; i++)
                #pragma unroll
                for (int j = 0; j < 4; j++)
                    if (tx * 4 + j > ty * 4 + i) sacc[i][j] = -1e30f;
        }

        float rmax[4];
        #pragma unroll
        for (int i = 0; i < 4; i++)
            rmax[i] = fmaxf(fmaxf(sacc[i][0], sacc[i][1]),
                            fmaxf(sacc[i][2], sacc[i][3]));
        #pragma unroll
        for (int off = 8; off; off >>= 1)
            #pragma unroll
            for (int i = 0; i < 4; i++)
                rmax[i] = fmaxf(rmax[i], __shfl_xor_sync(0xffffffffu, rmax[i], off));

        float p[4][4], rsum[4];
        #pragma unroll
        for (int i = 0; i < 4; i++) {
            float mn = fmaxf(m_i[i], rmax[i]);
            float sc = __expf(m_i[i] - mn);
            m_i[i] = mn;
            float rs = 0.f;
            #pragma unroll
            for (int j = 0; j < 4; j++) {
                p[i][j] = __expf(sacc[i][j] - mn);
                rs += p[i][j];
            }
            rsum[i] = rs;
            l_i[i] *= sc;
            #pragma unroll
            for (int j = 0; j < 4; j++) Ot[i][j] *= sc;
        }
        #pragma unroll
        for (int off = 8; off; off >>= 1)
            #pragma unroll
            for (int i = 0; i < 4; i++)
                rsum[i] += __shfl_xor_sync(0xffffffffu, rsum[i], off);
        #pragma unroll
        for (int i = 0; i < 4; i++) l_i[i] += rsum[i];

        #pragma unroll
        for (int i = 0; i < 4; i++)
            #pragma unroll
            for (int j = 0; j < 4; j++)
                Ps[(ty * 4 + i) * 64 + tx * 4 + j] = p[i][j];
        __syncthreads();

        #pragma unroll 4
        for (int n = 0; n < 64; n++) {
            float pv[4], kv[4];
            #pragma unroll
            for (int i = 0; i < 4; i++) pv[i] = Ps[(ty * 4 + i) * 64 + n];
            #pragma unroll
            for (int j = 0; j < 4; j++) kv[j] = Ks[n * 65 + tx * 4 + j];
            #pragma unroll
            for (int i = 0; i < 4; i++)
                #pragma unroll
                for (int j = 0; j < 4; j++)
                    Ot[i][j] = fmaf(pv[i], kv[j], Ot[i][j]);
        }
    }

    // Epilogue: normalize, gate, split to bf16 hi/lo
    #pragma unroll
    for (int i = 0; i < 4; i++) {
        float inv_l = 1.f / l_i[i];
        int r = qt * 64 + ty * 4 + i;
        size_t row = (size_t)(b * SS + r);
        const float4 g4 = *(const float4*)&qg[row * 4096 + 2048 + h * 64 + tx * 4];
        float vs[4];
        vs[0] = Ot[i][0] * inv_l * (1.f / (1.f + __expf(-g4.x)));
        vs[1] = Ot[i][1] * inv_l * (1.f / (1.f + __expf(-g4.y)));
        vs[2] = Ot[i][2] * inv_l * (1.f / (1.f + __expf(-g4.z)));
        vs[3] = Ot[i][3] * inv_l * (1.f / (1.f + __expf(-g4.w)));
        size_t o = row * 2048 + h * 64 + tx * 4;
        #pragma unroll
        for (int j = 0; j < 4; j++) {
            bf16 hh = __float2bfloat16(vs[j]);
            ctx_h[o + j] = hh;
            ctx_l[o + j] = __float2bfloat16(vs[j] - __bfloat162float(hh));
        }
    }
}

// ---------------------------------------------------------------------------
// Launch. Inputs (metadata order): hidden, cos, sin, mask(unused), wq, wk,
// wv(unused — reference computes v but never uses it), wo.
// ---------------------------------------------------------------------------
extern "C" void kernel_launch(void* const* d_in, const int* in_sizes, int n_in,
                              void* d_out, int out_size)
{
    const float* hidden = (const float*)d_in[0];
    const float* cosT   = (const float*)d_in[1];
    const float* sinT   = (const float*)d_in[2];
    const float* wq     = (const float*)d_in[4];
    const float* wk     = (const float*)d_in[5];
    const float* wo     = (const float*)d_in[7];
    float* out = (float*)d_out;

    float *qg, *kbuf;
    bf16 *hid_h, *hid_l, *wqt_h, *wqt_l, *wkt_h, *wkt_l, *wot_h, *wot_l, *ctx_h, *ctx_l;
    cudaGetSymbolAddress((void**)&qg,    g_qg);
    cudaGetSymbolAddress((void**)&kbuf,  g_k);
    cudaGetSymbolAddress((void**)&hid_h, g_hid_h);
    cudaGetSymbolAddress((void**)&hid_l, g_hid_l);
    cudaGetSymbolAddress((void**)&wqt_h, g_wqt_h);
    cudaGetSymbolAddress((void**)&wqt_l, g_wqt_l);
    cudaGetSymbolAddress((void**)&wkt_h, g_wkt_h);
    cudaGetSymbolAddress((void**)&wkt_l, g_wkt_l);
    cudaGetSymbolAddress((void**)&wot_h, g_wot_h);
    cudaGetSymbolAddress((void**)&wot_l, g_wot_l);
    cudaGetSymbolAddress((void**)&ctx_h, g_ctx_h);
    cudaGetSymbolAddress((void**)&ctx_l, g_ctx_l);

    cudaFuncSetAttribute(attn_kernel,
                         cudaFuncAttributeMaxDynamicSharedMemorySize, ATTN_SMEM);

    // 0) split hidden; transpose+split weights
    split_kernel<<<(ROWS * HID / 4 + 255) / 256, 256>>>(hidden, hid_h, hid_l, ROWS * HID / 4);
    transpose_split<<<dim3(4096 / 32, HID / 32), dim3(32, 8)>>>(wq, wqt_h, wqt_l, HID, 4096);
    transpose_split<<<dim3(512  / 32, HID / 32), dim3(32, 8)>>>(wk, wkt_h, wkt_l, HID, 512);
    transpose_split<<<dim3(2048 / 32, HID / 32), dim3(32, 8)>>>(wo, wot_h, wot_l, HID, 2048);

    // 1) qg = hidden @ wq   [4096 x 4096], K=2048  (tensor cores, 3-pass split)
    gemm_bf16split<<<dim3(4096 / 128, 4096 / 128), 256>>>(hid_h, hid_l, wqt_h, wqt_l,
                                                          qg, ROWS, 4096, HID);
    // 2) k = hidden @ wk    [4096 x 512]
    gemm_bf16split<<<dim3(512 / 128, 4096 / 128), 256>>>(hid_h, hid_l, wkt_h, wkt_l,
                                                         kbuf, ROWS, 512, HID);
    // 3) RoPE in place
    rope_kernel<<<(ROWS * NH * 32) / 256, 256>>>(qg, cosT, sinT, 4096, NH);
    rope_kernel<<<(ROWS * NKV * 32) / 256, 256>>>(kbuf, cosT, sinT, 512, NKV);
    // 4) attention + gate, writes split bf16 ctx
    attn_kernel<<<dim3(SS / 64, NH, BB), 256, ATTN_SMEM>>>(qg, kbuf, ctx_h, ctx_l);
    // 5) out = ctx @ wo     [4096 x 2048]
    gemm_bf16split<<<dim3(2048 / 128, 4096 / 128), 256>>>(ctx_h, ctx_l, wot_h, wot_l,
                                                          out, ROWS, HID, HID);
}

// round 5
// speedup vs baseline: 2.3655x; 2.3655x over previous
#include <cuda_runtime.h>
#include <cuda_bf16.h>
#include <cstdint>

// Problem constants
#define BB   2
#define SS   2048
#define HID  2048
#define NH   32
#define NKV  8
#define ROWS (BB * SS)          // 4096

typedef __nv_bfloat16 bf16;

// ---------------------------------------------------------------------------
// Scratch
// ---------------------------------------------------------------------------
__device__ float g_qg [(size_t)ROWS * 4096];   // q (RoPE'd in place) | gate
__device__ float g_k  [(size_t)ROWS * 512];    // k, RoPE'd in place
__device__ bf16  g_hid_h[(size_t)ROWS * HID],  g_hid_l[(size_t)ROWS * HID];
__device__ bf16  g_wqt_h[(size_t)4096 * HID],  g_wqt_l[(size_t)4096 * HID];
__device__ bf16  g_wkt_h[(size_t)512  * HID],  g_wkt_l[(size_t)512  * HID];
__device__ bf16  g_wot_h[(size_t)HID  * HID],  g_wot_l[(size_t)HID  * HID];
__device__ bf16  g_ctx_h[(size_t)ROWS * HID],  g_ctx_l[(size_t)ROWS * HID];

// ---------------------------------------------------------------------------
// Helpers
// ---------------------------------------------------------------------------
__device__ __forceinline__ uint32_t sptr(const void* p) {
    return (uint32_t)__cvta_generic_to_shared(p);
}
__device__ __forceinline__ void ldsm4(uint32_t* r, uint32_t addr) {
    asm volatile("ldmatrix.sync.aligned.m8n8.x4.shared.b16 {%0,%1,%2,%3}, [%4];"
                 : "=r"(r[0]), "=r"(r[1]), "=r"(r[2]), "=r"(r[3]) : "r"(addr));
}
__device__ __forceinline__ void mma16816(float* c, const uint32_t* a, const uint32_t* b)
{
    asm volatile(
        "mma.sync.aligned.m16n8k16.row.col.f32.bf16.bf16.f32 "
        "{%0,%1,%2,%3}, {%4,%5,%6,%7}, {%8,%9}, {%0,%1,%2,%3};"
        : "+f"(c[0]), "+f"(c[1]), "+f"(c[2]), "+f"(c[3])
        : "r"(a[0]), "r"(a[1]), "r"(a[2]), "r"(a[3]), "r"(b[0]), "r"(b[1]));
}
__device__ __forceinline__ uint32_t bfpack(float x, float y) {
    __nv_bfloat162 v = __floats2bfloat162_rn(x, y);
    return *(uint32_t*)&v;
}

// ---------------------------------------------------------------------------
// fp32 -> (bf16 hi, bf16 lo) split
// ---------------------------------------------------------------------------
__global__ void split_kernel(const float* __restrict__ src,
                             bf16* __restrict__ h, bf16* __restrict__ l, int n4)
{
    int i = blockIdx.x * blockDim.x + threadIdx.x;
    if (i >= n4) return;
    float4 v = ((const float4*)src)[i];
    bf16 h0 = __float2bfloat16(v.x), h1 = __float2bfloat16(v.y);
    bf16 h2 = __float2bfloat16(v.z), h3 = __float2bfloat16(v.w);
    h[i*4+0] = h0; h[i*4+1] = h1; h[i*4+2] = h2; h[i*4+3] = h3;
    l[i*4+0] = __float2bfloat16(v.x - __bfloat162float(h0));
    l[i*4+1] = __float2bfloat16(v.y - __bfloat162float(h1));
    l[i*4+2] = __float2bfloat16(v.z - __bfloat162float(h2));
    l[i*4+3] = __float2bfloat16(v.w - __bfloat162float(h3));
}

// ---------------------------------------------------------------------------
// Transpose + split: src [K][N] fp32 -> th/tl [N][K] bf16.
// ---------------------------------------------------------------------------
__global__ void transpose_split(const float* __restrict__ src,
                                bf16* __restrict__ th, bf16* __restrict__ tl,
                                int K, int N)
{
    __shared__ float tile[32][33];
    int kb = blockIdx.y * 32, nb = blockIdx.x * 32;
    int tx = threadIdx.x, ty = threadIdx.y;
    #pragma unroll
    for (int i = 0; i < 32; i += 8)
        tile[ty + i][tx] = src[(size_t)(kb + ty + i) * N + nb + tx];
    __syncthreads();
    #pragma unroll
    for (int i = 0; i < 32; i += 8) {
        float v = tile[tx][ty + i];
        bf16 hh = __float2bfloat16(v);
        size_t o = (size_t)(nb + ty + i) * K + kb + tx;
        th[o] = hh;
        tl[o] = __float2bfloat16(v - __bfloat162float(hh));
    }
}

// ---------------------------------------------------------------------------
// 3-pass bf16-split TN GEMM, ldmatrix fragment loads.
// CTA tile 128x128x32, 8 warps (2x4), warp tile 64x32.
// ---------------------------------------------------------------------------
#define GSTRIDE 40   // smem row stride in bf16 units

__global__ void __launch_bounds__(256, 1)
gemm_bf16split(const bf16* __restrict__ Ah, const bf16* __restrict__ Al,
               const bf16* __restrict__ Bh, const bf16* __restrict__ Bl,
               float* __restrict__ C, int M, int N, int K)
{
    __shared__ bf16 sAh[128 * GSTRIDE], sAl[128 * GSTRIDE];
    __shared__ bf16 sBh[128 * GSTRIDE], sBl[128 * GSTRIDE];

    const int tid  = threadIdx.x;
    const int warp = tid >> 5, lane = tid & 31;
    const int g    = lane >> 2, t = lane & 3;
    const int wm   = (warp & 1) * 64;
    const int wn   = (warp >> 1) * 32;
    const int brow = blockIdx.y * 128;
    const int bcol = blockIdx.x * 128;

    const int lrow  = lane & 15;
    const int khalf = lane >> 4;
    const int nrow  = (lane & 7) + ((lane >> 4) << 3);
    const int bkh   = (lane >> 3) & 1;

    const int r0 = tid >> 2,           k00 = (tid & 3) * 8;
    const int r1 = (tid + 256) >> 2,   k01 = ((tid + 256) & 3) * 8;

    const bf16* pAh = Ah + (size_t)brow * K;
    const bf16* pAl = Al + (size_t)brow * K;
    const bf16* pBh = Bh + (size_t)bcol * K;
    const bf16* pBl = Bl + (size_t)bcol * K;

    float acc[4][4][4] = {};
    uint4 ra_h[2], ra_l[2], rb_h[2], rb_l[2];

    ra_h[0] = *(const uint4*)(pAh + (size_t)r0 * K + k00);
    ra_h[1] = *(const uint4*)(pAh + (size_t)r1 * K + k01);
    ra_l[0] = *(const uint4*)(pAl + (size_t)r0 * K + k00);
    ra_l[1] = *(const uint4*)(pAl + (size_t)r1 * K + k01);
    rb_h[0] = *(const uint4*)(pBh + (size_t)r0 * K + k00);
    rb_h[1] = *(const uint4*)(pBh + (size_t)r1 * K + k01);
    rb_l[0] = *(const uint4*)(pBl + (size_t)r0 * K + k00);
    rb_l[1] = *(const uint4*)(pBl + (size_t)r1 * K + k01);

    for (int kt = 0; kt < K; kt += 32) {
        *(uint4*)&sAh[r0 * GSTRIDE + k00] = ra_h[0];
        *(uint4*)&sAh[r1 * GSTRIDE + k01] = ra_h[1];
        *(uint4*)&sAl[r0 * GSTRIDE + k00] = ra_l[0];
        *(uint4*)&sAl[r1 * GSTRIDE + k01] = ra_l[1];
        *(uint4*)&sBh[r0 * GSTRIDE + k00] = rb_h[0];
        *(uint4*)&sBh[r1 * GSTRIDE + k01] = rb_h[1];
        *(uint4*)&sBl[r0 * GSTRIDE + k00] = rb_l[0];
        *(uint4*)&sBl[r1 * GSTRIDE + k01] = rb_l[1];
        __syncthreads();

        if (kt + 32 < K) {
            int kn = kt + 32;
            ra_h[0] = *(const uint4*)(pAh + (size_t)r0 * K + kn + k00);
            ra_h[1] = *(const uint4*)(pAh + (size_t)r1 * K + kn + k01);
            ra_l[0] = *(const uint4*)(pAl + (size_t)r0 * K + kn + k00);
            ra_l[1] = *(const uint4*)(pAl + (size_t)r1 * K + kn + k01);
            rb_h[0] = *(const uint4*)(pBh + (size_t)r0 * K + kn + k00);
            rb_h[1] = *(const uint4*)(pBh + (size_t)r1 * K + kn + k01);
            rb_l[0] = *(const uint4*)(pBl + (size_t)r0 * K + kn + k00);
            rb_l[1] = *(const uint4*)(pBl + (size_t)r1 * K + kn + k01);
        }

        #pragma unroll
        for (int s = 0; s < 2; s++) {
            const int kc = s * 16;
            uint32_t fah[4][4], fal[4][4], fbh[2][4], fbl[2][4];

            #pragma unroll
            for (int ma = 0; ma < 4; ma++) {
                int ar = wm + ma * 16 + lrow;
                ldsm4(fah[ma], sptr(&sAh[ar * GSTRIDE + kc + khalf * 8]));
                ldsm4(fal[ma], sptr(&sAl[ar * GSTRIDE + kc + khalf * 8]));
            }
            #pragma unroll
            for (int np = 0; np < 2; np++) {
                int br = wn + np * 16 + nrow;
                ldsm4(fbh[np], sptr(&sBh[br * GSTRIDE + kc + bkh * 8]));
                ldsm4(fbl[np], sptr(&sBl[br * GSTRIDE + kc + bkh * 8]));
            }

            #pragma unroll
            for (int ma = 0; ma < 4; ma++)
                #pragma unroll
                for (int np = 0; np < 2; np++) {
                    #pragma unroll
                    for (int half = 0; half < 2; half++) {
                        int na = np * 2 + half;
                        mma16816(acc[ma][na], fah[ma], &fbh[np][half * 2]);
                        mma16816(acc[ma][na], fah[ma], &fbl[np][half * 2]);
                        mma16816(acc[ma][na], fal[ma], &fbh[np][half * 2]);
                    }
                }
        }
        __syncthreads();
    }

    #pragma unroll
    for (int ma = 0; ma < 4; ma++) {
        int row = brow + wm + ma * 16 + g;
        #pragma unroll
        for (int na = 0; na < 4; na++) {
            int col = bcol + wn + na * 8 + t * 2;
            float2 v0 = {acc[ma][na][0], acc[ma][na][1]};
            float2 v1 = {acc[ma][na][2], acc[ma][na][3]};
            *(float2*)&C[(size_t)row       * N + col] = v0;
            *(float2*)&C[(size_t)(row + 8) * N + col] = v1;
        }
    }
}

// ---------------------------------------------------------------------------
// RoPE (in place)
// ---------------------------------------------------------------------------
__global__ void rope_kernel(float* __restrict__ x,
                            const float* __restrict__ ct,
                            const float* __restrict__ st,
                            int stride, int nh)
{
    int idx = blockIdx.x * blockDim.x + threadIdx.x;
    int d = idx & 31;
    int h = (idx >> 5) % nh;
    int r = idx / (32 * nh);
    if (r >= ROWS) return;
    int s = r & (SS - 1);

    float* p = x + (size_t)r * stride + h * 64;
    float c0 = ct[s * 64 + d],      s0 = st[s * 64 + d];
    float c1 = ct[s * 64 + d + 32], s1 = st[s * 64 + d + 32];
    float x0 = p[d], x1 = p[d + 32];
    p[d]      = x0 * c0 - x1 * s0;
    p[d + 32] = x1 * c1 + x0 * s1;
}

// ---------------------------------------------------------------------------
// Tensor-core flash attention (bf16-split), reference quirk: out = P @ K.
// CTA: 128 q-rows x 64 k-cols per iter, 8 warps (16 q-rows each).
// ---------------------------------------------------------------------------
#define ASTR 72
#define QH_OFF  0
#define QL_OFF  9216
#define KH_OFF  18432
#define KL_OFF  23040
#define KTH_OFF 27648
#define KTL_OFF 32256
#define PH_OFF  36864
#define PL_OFF  46080
#define ATTN_SMEM (55296 * 2)   // 110592 B

__global__ void __launch_bounds__(256, 1)
attn_tc(const float* __restrict__ qg, const float* __restrict__ kbuf,
        bf16* __restrict__ ctx_h, bf16* __restrict__ ctx_l)
{
    extern __shared__ bf16 sm[];
    bf16* Qh  = sm + QH_OFF;  bf16* Ql  = sm + QL_OFF;
    bf16* Kh  = sm + KH_OFF;  bf16* Kl  = sm + KL_OFF;
    bf16* Kth = sm + KTH_OFF; bf16* Ktl = sm + KTL_OFF;
    bf16* Ph  = sm + PH_OFF;  bf16* Pl  = sm + PL_OFF;

    const int qt   = gridDim.x - 1 - blockIdx.x;
    const int h    = blockIdx.y;
    const int b    = blockIdx.z;
    const int kvh  = h >> 2;                     // G = 4
    const int tid  = threadIdx.x;
    const int warp = tid >> 5, lane = tid & 31;
    const int g    = lane >> 2, t = lane & 3;
    const int qbase = qt * 128;

    const int lrow  = lane & 15;
    const int khalf = lane >> 4;
    const int nrow  = (lane & 7) + ((lane >> 4) << 3);
    const int bkh   = (lane >> 3) & 1;

    // ---- load Q tile 128x64 fp32 -> split hi/lo ----
    {
        int row = tid >> 1;
        int c0  = (tid & 1) * 32;
        const float* src = qg + ((size_t)(b * SS + qbase + row)) * 4096 + h * 64 + c0;
        #pragma unroll
        for (int j = 0; j < 8; j++) {
            float4 v = *(const float4*)(src + j * 4);
            bf16 h0 = __float2bfloat16(v.x), h1 = __float2bfloat16(v.y);
            bf16 h2 = __float2bfloat16(v.z), h3 = __float2bfloat16(v.w);
            float l0 = v.x - __bfloat162float(h0), l1 = v.y - __bfloat162float(h1);
            float l2 = v.z - __bfloat162float(h2), l3 = v.w - __bfloat162float(h3);
            int o = row * ASTR + c0 + j * 4;
            *(uint32_t*)&Qh[o]     = bfpack(__bfloat162float(h0), __bfloat162float(h1));
            *(uint32_t*)&Qh[o + 2] = bfpack(__bfloat162float(h2), __bfloat162float(h3));
            *(uint32_t*)&Ql[o]     = bfpack(l0, l1);
            *(uint32_t*)&Ql[o + 2] = bfpack(l2, l3);
        }
    }

    float m0 = -1e30f, m1 = -1e30f, l0s = 0.f, l1s = 0.f;
    float oacc[8][4] = {};

    const int nkt = 2 * (qt + 1);
    for (int kti = 0; kti < nkt; kti++) {
        const int ktbase = kti * 64;
        __syncthreads();

        // ---- load K tile 64x64, split, store k-major and transposed ----
        {
            int kc = tid >> 2, dq = (tid & 3) * 16;
            const float* src = kbuf + ((size_t)(b * SS + ktbase + kc)) * 512 + kvh * 64 + dq;
            #pragma unroll
            for (int j = 0; j < 4; j++) {
                float4 v = *(const float4*)(src + j * 4);
                bf16 hh[4]; float ll[4];
                hh[0] = __float2bfloat16(v.x); ll[0] = v.x - __bfloat162float(hh[0]);
                hh[1] = __float2bfloat16(v.y); ll[1] = v.y - __bfloat162float(hh[1]);
                hh[2] = __float2bfloat16(v.z); ll[2] = v.z - __bfloat162float(hh[2]);
                hh[3] = __float2bfloat16(v.w); ll[3] = v.w - __bfloat162float(hh[3]);
                int o = kc * ASTR + dq + j * 4;
                *(uint32_t*)&Kh[o]     = bfpack(__bfloat162float(hh[0]), __bfloat162float(hh[1]));
                *(uint32_t*)&Kh[o + 2] = bfpack(__bfloat162float(hh[2]), __bfloat162float(hh[3]));
                *(uint32_t*)&Kl[o]     = bfpack(ll[0], ll[1]);
                *(uint32_t*)&Kl[o + 2] = bfpack(ll[2], ll[3]);
                #pragma unroll
                for (int e = 0; e < 4; e++) {
                    int d = dq + j * 4 + e;
                    Kth[d * ASTR + kc] = hh[e];
                    Ktl[d * ASTR + kc] = __float2bfloat16(ll[e]);
                }
            }
        }
        __syncthreads();

        // ---- S = Q K^T (3-pass split) ----
        float sacc[8][4] = {};
        #pragma unroll
        for (int ks = 0; ks < 4; ks++) {
            uint32_t ah[4], al[4];
            int ao = (warp * 16 + lrow) * ASTR + ks * 16 + khalf * 8;
            ldsm4(ah, sptr(&Qh[ao]));
            ldsm4(al, sptr(&Ql[ao]));
            #pragma unroll
            for (int np = 0; np < 4; np++) {
                uint32_t bh[4], bl[4];
                int bo = (np * 16 + nrow) * ASTR + ks * 16 + bkh * 8;
                ldsm4(bh, sptr(&Kh[bo]));
                ldsm4(bl, sptr(&Kl[bo]));
                #pragma unroll
                for (int half = 0; half < 2; half++) {
                    int na = np * 2 + half;
                    mma16816(sacc[na], ah, &bh[half * 2]);
                    mma16816(sacc[na], ah, &bl[half * 2]);
                    mma16816(sacc[na], al, &bh[half * 2]);
                }
            }
        }

        // ---- causal mask ----
        const int qrow0 = qbase + warp * 16 + g;
        if (kti >= nkt - 2) {
            #pragma unroll
            for (int na = 0; na < 8; na++) {
                int col = ktbase + na * 8 + t * 2;
                if (col     > qrow0)     sacc[na][0] = -1e30f;
                if (col + 1 > qrow0)     sacc[na][1] = -1e30f;
                if (col     > qrow0 + 8) sacc[na][2] = -1e30f;
                if (col + 1 > qrow0 + 8) sacc[na][3] = -1e30f;
            }
        }

        // ---- online softmax ----
        float rmax0 = -1e30f, rmax1 = -1e30f;
        #pragma unroll
        for (int na = 0; na < 8; na++) {
            rmax0 = fmaxf(rmax0, fmaxf(sacc[na][0], sacc[na][1]));
            rmax1 = fmaxf(rmax1, fmaxf(sacc[na][2], sacc[na][3]));
        }
        rmax0 = fmaxf(rmax0, __shfl_xor_sync(0xffffffffu, rmax0, 1));
        rmax0 = fmaxf(rmax0, __shfl_xor_sync(0xffffffffu, rmax0, 2));
        rmax1 = fmaxf(rmax1, __shfl_xor_sync(0xffffffffu, rmax1, 1));
        rmax1 = fmaxf(rmax1, __shfl_xor_sync(0xffffffffu, rmax1, 2));

        float mn0 = fmaxf(m0, rmax0), mn1 = fmaxf(m1, rmax1);
        float sc0 = __expf(m0 - mn0), sc1 = __expf(m1 - mn1);
        m0 = mn0; m1 = mn1;

        float rs0 = 0.f, rs1 = 0.f;
        const int prow0 = warp * 16 + g;
        #pragma unroll
        for (int na = 0; na < 8; na++) {
            float p0 = __expf(sacc[na][0] - mn0);
            float p1 = __expf(sacc[na][1] - mn0);
            float p2 = __expf(sacc[na][2] - mn1);
            float p3 = __expf(sacc[na][3] - mn1);
            rs0 += p0 + p1;  rs1 += p2 + p3;
            int c = na * 8 + t * 2;
            bf16 hp0 = __float2bfloat16(p0), hp1 = __float2bfloat16(p1);
            bf16 hp2 = __float2bfloat16(p2), hp3 = __float2bfloat16(p3);
            *(uint32_t*)&Ph[prow0 * ASTR + c]       = bfpack(__bfloat162float(hp0), __bfloat162float(hp1));
            *(uint32_t*)&Ph[(prow0 + 8) * ASTR + c] = bfpack(__bfloat162float(hp2), __bfloat162float(hp3));
            *(uint32_t*)&Pl[prow0 * ASTR + c]       =
                bfpack(p0 - __bfloat162float(hp0), p1 - __bfloat162float(hp1));
            *(uint32_t*)&Pl[(prow0 + 8) * ASTR + c] =
                bfpack(p2 - __bfloat162float(hp2), p3 - __bfloat162float(hp3));
        }
        rs0 += __shfl_xor_sync(0xffffffffu, rs0, 1);
        rs0 += __shfl_xor_sync(0xffffffffu, rs0, 2);
        rs1 += __shfl_xor_sync(0xffffffffu, rs1, 1);
        rs1 += __shfl_xor_sync(0xffffffffu, rs1, 2);
        l0s = l0s * sc0 + rs0;
        l1s = l1s * sc1 + rs1;

        #pragma unroll
        for (int na = 0; na < 8; na++) {
            oacc[na][0] *= sc0; oacc[na][1] *= sc0;
            oacc[na][2] *= sc1; oacc[na][3] *= sc1;
        }
        __syncthreads();

        // ---- O += P @ K  (B = Kt, 3-pass split) ----
        #pragma unroll
        for (int ks = 0; ks < 4; ks++) {
            uint32_t ah[4], al[4];
            int ao = (warp * 16 + lrow) * ASTR + ks * 16 + khalf * 8;
            ldsm4(ah, sptr(&Ph[ao]));
            ldsm4(al, sptr(&Pl[ao]));
            #pragma unroll
            for (int np = 0; np < 4; np++) {
                uint32_t bh[4], bl[4];
                int bo = (np * 16 + nrow) * ASTR + ks * 16 + bkh * 8;
                ldsm4(bh, sptr(&Kth[bo]));
                ldsm4(bl, sptr(&Ktl[bo]));
                #pragma unroll
                for (int half = 0; half < 2; half++) {
                    int na = np * 2 + half;
                    mma16816(oacc[na], ah, &bh[half * 2]);
                    mma16816(oacc[na], ah, &bl[half * 2]);
                    mma16816(oacc[na], al, &bh[half * 2]);
                }
            }
        }
    }

    // ---- epilogue: normalize, gate, split to ctx hi/lo ----
    const float inv0 = 1.f / l0s, inv1 = 1.f / l1s;
    const size_t grow0 = (size_t)(b * SS + qbase + warp * 16 + g);
    #pragma unroll
    for (int na = 0; na < 8; na++) {
        int col = na * 8 + t * 2;
        float2 gv0 = *(const float2*)&qg[grow0 * 4096 + 2048 + h * 64 + col];
        float2 gv1 = *(const float2*)&qg[(grow0 + 8) * 4096 + 2048 + h * 64 + col];
        float v0 = oacc[na][0] * inv0 * (1.f / (1.f + __expf(-gv0.x)));
        float v1 = oacc[na][1] * inv0 * (1.f / (1.f + __expf(-gv0.y)));
        float v2 = oacc[na][2] * inv1 * (1.f / (1.f + __expf(-gv1.x)));
        float v3 = oacc[na][3] * inv1 * (1.f / (1.f + __expf(-gv1.y)));
        bf16 h0 = __float2bfloat16(v0), h1 = __float2bfloat16(v1);
        bf16 h2 = __float2bfloat16(v2), h3 = __float2bfloat16(v3);
        size_t o0 = grow0 * 2048 + h * 64 + col;
        size_t o1 = (grow0 + 8) * 2048 + h * 64 + col;
        *(uint32_t*)&ctx_h[o0] = bfpack(__bfloat162float(h0), __bfloat162float(h1));
        *(uint32_t*)&ctx_h[o1] = bfpack(__bfloat162float(h2), __bfloat162float(h3));
        *(uint32_t*)&ctx_l[o0] = bfpack(v0 - __bfloat162float(h0), v1 - __bfloat162float(h1));
        *(uint32_t*)&ctx_l[o1] = bfpack(v2 - __bfloat162float(h2), v3 - __bfloat162float(h3));
    }
}

// ---------------------------------------------------------------------------
// Launch. Inputs: hidden, cos, sin, mask(unused), wq, wk, wv(unused), wo.
// ---------------------------------------------------------------------------
extern "C" void kernel_launch(void* const* d_in, const int* in_sizes, int n_in,
                              void* d_out, int out_size)
{
    const float* hidden = (const float*)d_in[0];
    const float* cosT   = (const float*)d_in[1];
    const float* sinT   = (const float*)d_in[2];
    const float* wq     = (const float*)d_in[4];
    const float* wk     = (const float*)d_in[5];
    const float* wo     = (const float*)d_in[7];
    float* out = (float*)d_out;

    float *qg, *kbuf;
    bf16 *hid_h, *hid_l, *wqt_h, *wqt_l, *wkt_h, *wkt_l, *wot_h, *wot_l, *ctx_h, *ctx_l;
    cudaGetSymbolAddress((void**)&qg,    g_qg);
    cudaGetSymbolAddress((void**)&kbuf,  g_k);
    cudaGetSymbolAddress((void**)&hid_h, g_hid_h);
    cudaGetSymbolAddress((void**)&hid_l, g_hid_l);
    cudaGetSymbolAddress((void**)&wqt_h, g_wqt_h);
    cudaGetSymbolAddress((void**)&wqt_l, g_wqt_l);
    cudaGetSymbolAddress((void**)&wkt_h, g_wkt_h);
    cudaGetSymbolAddress((void**)&wkt_l, g_wkt_l);
    cudaGetSymbolAddress((void**)&wot_h, g_wot_h);
    cudaGetSymbolAddress((void**)&wot_l, g_wot_l);
    cudaGetSymbolAddress((void**)&ctx_h, g_ctx_h);
    cudaGetSymbolAddress((void**)&ctx_l, g_ctx_l);

    cudaFuncSetAttribute(attn_tc,
                         cudaFuncAttributeMaxDynamicSharedMemorySize, ATTN_SMEM);

    split_kernel<<<(ROWS * HID / 4 + 255) / 256, 256>>>(hidden, hid_h, hid_l, ROWS * HID / 4);
    transpose_split<<<dim3(4096 / 32, HID / 32), dim3(32, 8)>>>(wq, wqt_h, wqt_l, HID, 4096);
    transpose_split<<<dim3(512  / 32, HID / 32), dim3(32, 8)>>>(wk, wkt_h, wkt_l, HID, 512);
    transpose_split<<<dim3(2048 / 32, HID / 32), dim3(32, 8)>>>(wo, wot_h, wot_l, HID, 2048);

    gemm_bf16split<<<dim3(4096 / 128, 4096 / 128), 256>>>(hid_h, hid_l, wqt_h, wqt_l,
                                                          qg, ROWS, 4096, HID);
    gemm_bf16split<<<dim3(512 / 128, 4096 / 128), 256>>>(hid_h, hid_l, wkt_h, wkt_l,
                                                         kbuf, ROWS, 512, HID);
    rope_kernel<<<(ROWS * NH * 32) / 256, 256>>>(qg, cosT, sinT, 4096, NH);
    rope_kernel<<<(ROWS * NKV * 32) / 256, 256>>>(kbuf, cosT, sinT, 512, NKV);

    attn_tc<<<dim3(SS / 128, NH, BB), 256, ATTN_SMEM>>>(qg, kbuf, ctx_h, ctx_l);

    gemm_bf16split<<<dim3(2048 / 128, 4096 / 128), 256>>>(ctx_h, ctx_l, wot_h, wot_l,
                                                          out, ROWS, HID, HID);
}